// round 1
// baseline (speedup 1.0000x reference)
#include <cuda_runtime.h>
#include <cuda_fp16.h>
#include <cstdint>

#define B 64
#define F 4
#define M 4096
#define D 1024
#define ITERS 15
#define WPD 16   // 64-bit words per D-dim vector

// ---------------- device scratch (no allocs allowed) ----------------
__device__ unsigned long long g_cb_bits[F][WPD][M];   // codebook bits, [f][word][m]  (2 MB)
__device__ __half             g_cbT[F][D][M];         // codebook +-1 fp16, [f][d][m] (32 MB)
__device__ unsigned long long g_in_bits[B][WPD];
__device__ unsigned long long g_est[B][F][WPD];       // current estimates (bits, 1 = -1)
__device__ __half             g_sim[F][B][M];         // similarity matrix (exact ints in fp16)
__device__ unsigned char      g_upd[B][F][D];         // update signs (1 = -1)
__device__ int                g_diff[ITERS];          // per-iteration "changed" flags

// ---------------- helpers ----------------
__device__ __forceinline__ unsigned long long pack64(const float* p) {
    unsigned long long w = 0ULL;
    #pragma unroll
    for (int t = 0; t < 16; t++) {
        float4 v = reinterpret_cast<const float4*>(p)[t];
        w |= ((unsigned long long)(v.x < 0.f)) << (4 * t + 0);
        w |= ((unsigned long long)(v.y < 0.f)) << (4 * t + 1);
        w |= ((unsigned long long)(v.z < 0.f)) << (4 * t + 2);
        w |= ((unsigned long long)(v.w < 0.f)) << (4 * t + 3);
    }
    return w;
}

__device__ __forceinline__ void mma16816(float* c,
                                         unsigned a0, unsigned a1, unsigned a2, unsigned a3,
                                         unsigned b0, unsigned b1) {
    asm volatile(
        "mma.sync.aligned.m16n8k16.row.col.f32.f16.f16.f32 "
        "{%0,%1,%2,%3}, {%4,%5,%6,%7}, {%8,%9}, {%0,%1,%2,%3};"
        : "+f"(c[0]), "+f"(c[1]), "+f"(c[2]), "+f"(c[3])
        : "r"(a0), "r"(a1), "r"(a2), "r"(a3), "r"(b0), "r"(b1));
}

// ---------------- packing kernels ----------------
__global__ void k_pack_small(const float* __restrict__ input,
                             const float* __restrict__ est0) {
    int idx = blockIdx.x * 256 + threadIdx.x;
    if (idx < B * WPD) {
        int b = idx >> 4, j = idx & 15;
        g_in_bits[b][j] = pack64(input + b * D + j * 64);
    } else if (idx < B * WPD + B * F * WPD) {
        int w = idx - B * WPD;
        int b = w >> 6, f = (w >> 4) & 3, j = w & 15;
        g_est[b][f][j] = pack64(est0 + (size_t)(b * F + f) * D + j * 64);
    } else if (idx < B * WPD + B * F * WPD + ITERS) {
        g_diff[idx - (B * WPD + B * F * WPD)] = 0;
    }
}

__global__ void k_pack_cb(const float* __restrict__ cb) {
    int idx = blockIdx.x * 256 + threadIdx.x;   // F*WPD*M total
    int m = idx & (M - 1);
    int j = (idx >> 12) & 15;
    int f = idx >> 16;
    g_cb_bits[f][j][m] = pack64(cb + ((size_t)(f * M + m)) * D + j * 64);
}

__global__ void k_pack_cbT(const float* __restrict__ cb) {
    __shared__ float sh[32][33];
    int f = blockIdx.z;
    int d0 = blockIdx.x * 32, m0 = blockIdx.y * 32;
    int tx = threadIdx.x, ty = threadIdx.y;
    sh[ty][tx] = cb[((size_t)(f * M + m0 + ty)) * D + d0 + tx];
    __syncthreads();
    int d = d0 + ty, m = m0 + tx;
    float v = sh[tx][ty];
    g_cbT[f][d][m] = __float2half(v < 0.f ? -1.f : 1.f);
}

// ---------------- per-iteration kernels ----------------
// mode 0: sim of new_est (unbound) vs codebooks.  mode 1: sim of est vs codebooks.
__global__ void k_sim(int mode) {
    int f = blockIdx.x;
    int m = blockIdx.y * 256 + threadIdx.x;
    int b0 = blockIdx.z * 8;
    __shared__ unsigned long long sh[8][WPD];
    if (threadIdx.x < 128) {
        int bb = threadIdx.x >> 4, j = threadIdx.x & 15;
        int b = b0 + bb;
        unsigned long long e = g_est[b][f][j];
        if (mode == 0) {
            unsigned long long tot = g_in_bits[b][j];
            #pragma unroll
            for (int ff = 0; ff < F; ff++) tot ^= g_est[b][ff][j];
            e ^= tot;   // new_est = input ^ prod(all) ^ est_f
        }
        sh[bb][j] = e;
    }
    __syncthreads();
    int acc[8];
    #pragma unroll
    for (int i = 0; i < 8; i++) acc[i] = 0;
    #pragma unroll
    for (int j = 0; j < WPD; j++) {
        unsigned long long w = g_cb_bits[f][j][m];
        #pragma unroll
        for (int bb = 0; bb < 8; bb++) acc[bb] += __popcll(w ^ sh[bb][j]);
    }
    #pragma unroll
    for (int bb = 0; bb < 8; bb++)
        g_sim[f][b0 + bb][m] = __int2half_rn(D - 2 * acc[bb]);
}

// upd[b,f,d] = sign( sum_m sim[b,f,m] * C[f,m,d] ), tensor-core GEMM.
// Per f: A = sim (64 x 4096 fp16), B = cbT (d-major, k=m), out 64 x 1024.
__global__ void __launch_bounds__(128) k_upd() {
    int f  = blockIdx.x;
    int nb = blockIdx.y * 32;
    __shared__ __align__(16) __half shA[64][72];
    __shared__ __align__(16) __half shB[32][72];
    int tid = threadIdx.x;
    int wid = tid >> 5, lane = tid & 31, g = lane >> 2, q = lane & 3;
    float acc[4][4];
    #pragma unroll
    for (int i = 0; i < 4; i++)
        #pragma unroll
        for (int jj = 0; jj < 4; jj++) acc[i][jj] = 0.f;

    for (int kc = 0; kc < M; kc += 64) {
        #pragma unroll
        for (int r = 0; r < 8; r++) {       // A: 64 rows x 16 uint2
            int idx = tid + 128 * r;
            int row = idx >> 4, i = idx & 15;
            *(uint2*)&shA[row][i * 4] =
                *(const uint2*)&g_sim[f][row][kc + i * 4];
        }
        #pragma unroll
        for (int r = 0; r < 4; r++) {       // B: 32 rows x 16 uint2
            int idx = tid + 128 * r;
            int row = idx >> 4, i = idx & 15;
            *(uint2*)&shB[row][i * 4] =
                *(const uint2*)&g_cbT[f][nb + row][kc + i * 4];
        }
        __syncthreads();
        #pragma unroll
        for (int kk = 0; kk < 64; kk += 16) {
            int r0 = wid * 16 + g;
            unsigned a0 = *(const unsigned*)&shA[r0    ][kk + q * 2];
            unsigned a1 = *(const unsigned*)&shA[r0 + 8][kk + q * 2];
            unsigned a2 = *(const unsigned*)&shA[r0    ][kk + 8 + q * 2];
            unsigned a3 = *(const unsigned*)&shA[r0 + 8][kk + 8 + q * 2];
            #pragma unroll
            for (int nt = 0; nt < 4; nt++) {
                unsigned b0v = *(const unsigned*)&shB[nt * 8 + g][kk + q * 2];
                unsigned b1v = *(const unsigned*)&shB[nt * 8 + g][kk + 8 + q * 2];
                mma16816(acc[nt], a0, a1, a2, a3, b0v, b1v);
            }
        }
        __syncthreads();
    }
    int r0 = wid * 16 + g;
    #pragma unroll
    for (int nt = 0; nt < 4; nt++) {
        int c0 = nb + nt * 8 + q * 2;
        g_upd[r0    ][f][c0    ] = (unsigned char)(acc[nt][0] < 0.f);
        g_upd[r0    ][f][c0 + 1] = (unsigned char)(acc[nt][1] < 0.f);
        g_upd[r0 + 8][f][c0    ] = (unsigned char)(acc[nt][2] < 0.f);
        g_upd[r0 + 8][f][c0 + 1] = (unsigned char)(acc[nt][3] < 0.f);
    }
}

// pack upd bytes -> bits, compare with old est, update est, record convergence
__global__ void k_fin(int t) {
    int idx = blockIdx.x * 256 + threadIdx.x;   // 4096 words
    int b = idx >> 6, f = (idx >> 4) & 3, j = idx & 15;
    const unsigned long long* q =
        (const unsigned long long*)&g_upd[b][f][j * 64];
    unsigned long long w = 0ULL;
    #pragma unroll
    for (int s = 0; s < 8; s++) {
        unsigned long long x = q[s];
        #pragma unroll
        for (int k = 0; k < 8; k++)
            w |= ((x >> (8 * k)) & 1ULL) << (8 * s + k);
    }
    bool diff = (w != g_est[b][f][j]);
    g_est[b][f][j] = w;
    unsigned bal = __ballot_sync(0xffffffffu, diff);
    if ((threadIdx.x & 31) == 0 && bal) atomicOr(&g_diff[t], 1);
}

// ---------------- output kernels ----------------
__global__ void k_argmax(float* __restrict__ out) {
    int bf = blockIdx.x;
    int b = bf >> 2, f = bf & 3;
    const __half* s = g_sim[f][b];
    int best = -1;
    #pragma unroll
    for (int i = 0; i < 16; i++) {
        int m = threadIdx.x + i * 256;
        int v = (int)__half2float(s[m]);
        int a = v < 0 ? -v : v;
        int key = (a << 12) | (4095 - m);   // max abs, then lowest m
        if (key > best) best = key;
    }
    __shared__ int sh[256];
    sh[threadIdx.x] = best;
    __syncthreads();
    for (int step = 128; step > 0; step >>= 1) {
        if (threadIdx.x < step) {
            if (sh[threadIdx.x + step] > sh[threadIdx.x])
                sh[threadIdx.x] = sh[threadIdx.x + step];
        }
        __syncthreads();
    }
    if (threadIdx.x == 0)
        out[bf] = (float)(4095 - (sh[0] & 4095));
}

__global__ void k_est_out(float* __restrict__ out) {
    int idx = blockIdx.x * 256 + threadIdx.x;   // b*F*D + f*D + d
    int d = idx & (D - 1);
    int f = (idx >> 10) & 3;
    int b = idx >> 12;
    unsigned long long w = g_est[b][f][d >> 6];
    out[idx] = ((w >> (d & 63)) & 1ULL) ? -1.f : 1.f;
}

__global__ void k_misc(float* __restrict__ out) {
    int iters = ITERS, conv = 0;
    for (int t = 0; t < ITERS; t++) {
        if (g_diff[t] == 0) { iters = t + 1; conv = 1; break; }
    }
    out[0] = (float)iters;
    out[1] = (float)conv;
}

// ---------------- launcher ----------------
extern "C" void kernel_launch(void* const* d_in, const int* in_sizes, int n_in,
                              void* d_out, int out_size) {
    const float* input = nullptr;
    const float* est0  = nullptr;
    const float* cb    = nullptr;
    for (int i = 0; i < n_in; i++) {
        if      (in_sizes[i] == B * D)     input = (const float*)d_in[i];
        else if (in_sizes[i] == B * F * D) est0  = (const float*)d_in[i];
        else if (in_sizes[i] == F * M * D) cb    = (const float*)d_in[i];
    }
    if (!input) input = (const float*)d_in[0];
    if (!est0)  est0  = (const float*)d_in[1];
    if (!cb)    cb    = (const float*)d_in[2];
    float* out = (float*)d_out;

    k_pack_small<<<(B * WPD + B * F * WPD + ITERS + 255) / 256, 256>>>(input, est0);
    k_pack_cb<<<F * WPD * M / 256, 256>>>(cb);
    {
        dim3 tg(D / 32, M / 32, F);
        dim3 tb(32, 32);
        k_pack_cbT<<<tg, tb>>>(cb);
    }

    for (int t = 0; t < ITERS; t++) {
        k_sim<<<dim3(F, M / 256, B / 8), 256>>>(0);
        k_upd<<<dim3(F, D / 32), 128>>>();
        k_fin<<<16, 256>>>(t);
    }

    // cleanup similarity on final estimates
    k_sim<<<dim3(F, M / 256, B / 8), 256>>>(1);

    // output layout (float32): assume order (outcome, est, iters, conv)
    const long long n_out = B * F;                 // 256
    const long long n_est = (long long)B * F * D;  // 262144
    long long off_outcome = -1, off_est = -1, off_misc = -1;
    if ((long long)out_size >= n_out + n_est + 2) {
        off_outcome = 0; off_est = n_out; off_misc = n_out + n_est;
    } else if ((long long)out_size == n_est) {
        off_est = 0;
    } else if ((long long)out_size == n_out) {
        off_outcome = 0;
    } else if ((long long)out_size == n_out + n_est) {
        off_outcome = 0; off_est = n_out;
    } else {
        off_outcome = 0;
    }

    if (off_outcome >= 0) k_argmax<<<B * F, 256>>>(out + off_outcome);
    if (off_est     >= 0) k_est_out<<<(B * F * D) / 256, 256>>>(out + off_est);
    if (off_misc    >= 0) k_misc<<<1, 1>>>(out + off_misc);
}

// round 3
// speedup vs baseline: 5.0668x; 5.0668x over previous
#include <cuda_runtime.h>
#include <cuda_fp16.h>
#include <cstdint>

#define B 64
#define F 4
#define M 4096
#define D 1024
#define ITERS 15
#define WPD 16   // 64-bit words per D-dim vector
#define WPM 64   // 64-bit words per M-dim vector
#define FINAL_BUF (ITERS & 1)

// ---------------- device scratch (no allocs allowed) ----------------
__device__ unsigned long long g_cb_bits[F][WPD][M];   // codebook bits over d, [f][word][m] (2 MB)
__device__ unsigned long long g_cbcol[F][D][WPM];     // codebook bits over m, [f][d][word] (2 MB)
__device__ __half             g_G[F][D][D];           // Gram matrix C^T C, exact even ints (8 MB)
__device__ unsigned long long g_in_bits[B][WPD];
__device__ unsigned long long g_est[2][B][F][WPD];    // double-buffered estimates (bit 1 = -1)
__device__ __half             g_sim[F][B][M];         // final similarity (exact ints in fp16)
__device__ int                g_diff[ITERS];          // per-iteration "changed" flags

// ---------------- helpers ----------------
__device__ __forceinline__ unsigned long long pack64(const float* p) {
    unsigned long long w = 0ULL;
    #pragma unroll
    for (int t = 0; t < 16; t++) {
        float4 v = reinterpret_cast<const float4*>(p)[t];
        w |= ((unsigned long long)(v.x < 0.f)) << (4 * t + 0);
        w |= ((unsigned long long)(v.y < 0.f)) << (4 * t + 1);
        w |= ((unsigned long long)(v.z < 0.f)) << (4 * t + 2);
        w |= ((unsigned long long)(v.w < 0.f)) << (4 * t + 3);
    }
    return w;
}

__device__ __forceinline__ void mma16816(float* c,
                                         unsigned a0, unsigned a1, unsigned a2, unsigned a3,
                                         unsigned b0, unsigned b1) {
    asm volatile(
        "mma.sync.aligned.m16n8k16.row.col.f32.f16.f16.f32 "
        "{%0,%1,%2,%3}, {%4,%5,%6,%7}, {%8,%9}, {%0,%1,%2,%3};"
        : "+f"(c[0]), "+f"(c[1]), "+f"(c[2]), "+f"(c[3])
        : "r"(a0), "r"(a1), "r"(a2), "r"(a3), "r"(b0), "r"(b1));
}

// bits (2 low bits, 1 = negative) -> packed half2 {+-1, +-1}
__device__ __forceinline__ unsigned bits2h2(unsigned bits) {
    return 0x3C003C00u ^ ((bits & 1u) << 15) ^ ((bits & 2u) << 30);
}

// ---------------- packing kernels ----------------
__global__ void k_pack_small(const float* __restrict__ input,
                             const float* __restrict__ est0) {
    int idx = blockIdx.x * 256 + threadIdx.x;
    if (idx < B * WPD) {
        int b = idx >> 4, j = idx & 15;
        g_in_bits[b][j] = pack64(input + b * D + j * 64);
    } else if (idx < B * WPD + B * F * WPD) {
        int w = idx - B * WPD;
        int b = w >> 6, f = (w >> 4) & 3, j = w & 15;
        g_est[0][b][f][j] = pack64(est0 + (size_t)(b * F + f) * D + j * 64);
    } else if (idx < B * WPD + B * F * WPD + ITERS) {
        g_diff[idx - (B * WPD + B * F * WPD)] = 0;
    }
}

__global__ void k_pack_cb(const float* __restrict__ cb) {
    int idx = blockIdx.x * 256 + threadIdx.x;   // F*WPD*M total
    int m = idx & (M - 1);
    int j = (idx >> 12) & 15;
    int f = idx >> 16;
    g_cb_bits[f][j][m] = pack64(cb + ((size_t)(f * M + m)) * D + j * 64);
}

// bits over m for each (f, d): g_cbcol[f][d][j], bit k <-> m = j*64+k
__global__ void k_pack_cbcol(const float* __restrict__ cb) {
    int idx = blockIdx.x * 256 + threadIdx.x;   // (f*WPM + j)*D + d
    int d = idx & (D - 1);
    int rest = idx >> 10;
    int j = rest & 63;
    int f = rest >> 6;
    const float* base = cb + ((size_t)f * M + (size_t)j * 64) * D + d;
    unsigned long long w = 0ULL;
    #pragma unroll
    for (int k = 0; k < 64; k++) {
        float v = base[(size_t)k * D];
        w |= ((unsigned long long)(v < 0.f)) << k;
    }
    g_cbcol[f][d][j] = w;
}

// ---------------- Gram matrix: G[f][a][b] = dot(col_a, col_b) = M - 2*popc ----------------
__global__ void __launch_bounds__(256) k_gram() {
    __shared__ unsigned long long shX[32][WPM + 1];
    __shared__ unsigned long long shY[32][WPM + 1];
    int f  = blockIdx.x;
    int x0 = blockIdx.y * 32;
    int y0 = blockIdx.z * 32;
    int tid = threadIdx.x;
    #pragma unroll
    for (int r = 0; r < 8; r++) {
        int w = tid + 256 * r;
        int row = w >> 6, col = w & 63;
        shX[row][col] = g_cbcol[f][x0 + row][col];
        shY[row][col] = g_cbcol[f][y0 + row][col];
    }
    __syncthreads();
    int x  = tid >> 3;
    int y4 = (tid & 7) * 4;
    int acc0 = 0, acc1 = 0, acc2 = 0, acc3 = 0;
    #pragma unroll
    for (int w = 0; w < WPM; w++) {
        unsigned long long xv = shX[x][w];
        acc0 += __popcll(xv ^ shY[y4 + 0][w]);
        acc1 += __popcll(xv ^ shY[y4 + 1][w]);
        acc2 += __popcll(xv ^ shY[y4 + 2][w]);
        acc3 += __popcll(xv ^ shY[y4 + 3][w]);
    }
    g_G[f][x0 + x][y0 + y4 + 0] = __int2half_rn(M - 2 * acc0);
    g_G[f][x0 + x][y0 + y4 + 1] = __int2half_rn(M - 2 * acc1);
    g_G[f][x0 + x][y0 + y4 + 2] = __int2half_rn(M - 2 * acc2);
    g_G[f][x0 + x][y0 + y4 + 3] = __int2half_rn(M - 2 * acc3);
}

// ---------------- fused iteration kernel ----------------
// upd = sign(new_est @ G[f]), pack to bits, diff flag, double-buffered est.
// grid = (F, D/64), block = 256 (8 warps). Block tile: 64(B) x 64(d), K = D.
__global__ void __launch_bounds__(256) k_iter(int t) {
    const int rbuf = t & 1, wbuf = (t & 1) ^ 1;
    __shared__ unsigned long long snew[64][WPD + 1];   // new_est bits, this f
    __shared__ __align__(16) __half shB[64][72];       // G chunk [d][k]
    __shared__ unsigned char sbytes[64][64];           // sign bytes

    int f  = blockIdx.x;
    int jd = blockIdx.y;           // word index == d-tile (64 d per word)
    int tid = threadIdx.x;
    int wid = tid >> 5, lane = tid & 31, g = lane >> 2, q = lane & 3;
    int mrow0 = (wid >> 1) * 16;   // 4 row groups of 16
    int ncol0 = (wid & 1) * 32;    // 2 col groups of 32

    // new_est bits: in ^ (xor over all f) ^ est_f
    #pragma unroll
    for (int r = 0; r < 4; r++) {
        int idx = tid + 256 * r;   // 1024 words
        int b = idx >> 4, j = idx & 15;
        unsigned long long tot = g_in_bits[b][j];
        #pragma unroll
        for (int ff = 0; ff < F; ff++) tot ^= g_est[rbuf][b][ff][j];
        snew[b][j] = tot ^ g_est[rbuf][b][f][j];
    }
    __syncthreads();

    float acc[4][4];
    #pragma unroll
    for (int i = 0; i < 4; i++)
        #pragma unroll
        for (int jj = 0; jj < 4; jj++) acc[i][jj] = 0.f;

    const int d0 = jd * 64;
    for (int kc = 0; kc < D; kc += 64) {
        // load G chunk: 64 rows (d) x 64 halves (k) = 512 uint4, 2 per thread
        #pragma unroll
        for (int r = 0; r < 2; r++) {
            int idx = tid + 256 * r;
            int row = idx >> 3, seg = idx & 7;
            *(uint4*)&shB[row][seg * 8] =
                *(const uint4*)&g_G[f][d0 + row][kc + seg * 8];
        }
        __syncthreads();
        unsigned long long w0 = snew[mrow0 + g][kc >> 6];
        unsigned long long w1 = snew[mrow0 + 8 + g][kc >> 6];
        #pragma unroll
        for (int kk = 0; kk < 64; kk += 16) {
            unsigned a0 = bits2h2((unsigned)(w0 >> (kk + q * 2)) & 3u);
            unsigned a1 = bits2h2((unsigned)(w1 >> (kk + q * 2)) & 3u);
            unsigned a2 = bits2h2((unsigned)(w0 >> (kk + 8 + q * 2)) & 3u);
            unsigned a3 = bits2h2((unsigned)(w1 >> (kk + 8 + q * 2)) & 3u);
            #pragma unroll
            for (int nt = 0; nt < 4; nt++) {
                unsigned b0v = *(const unsigned*)&shB[ncol0 + nt * 8 + g][kk + q * 2];
                unsigned b1v = *(const unsigned*)&shB[ncol0 + nt * 8 + g][kk + 8 + q * 2];
                mma16816(acc[nt], a0, a1, a2, a3, b0v, b1v);
            }
        }
        __syncthreads();
    }

    // epilogue: sign bytes -> smem
    int r0 = mrow0 + g;
    #pragma unroll
    for (int nt = 0; nt < 4; nt++) {
        int c0 = ncol0 + nt * 8 + q * 2;
        sbytes[r0    ][c0    ] = (unsigned char)(acc[nt][0] < 0.f);
        sbytes[r0    ][c0 + 1] = (unsigned char)(acc[nt][1] < 0.f);
        sbytes[r0 + 8][c0    ] = (unsigned char)(acc[nt][2] < 0.f);
        sbytes[r0 + 8][c0 + 1] = (unsigned char)(acc[nt][3] < 0.f);
    }
    __syncthreads();

    if (tid < 64) {
        const unsigned long long* q8 = (const unsigned long long*)sbytes[tid];
        unsigned long long w = 0ULL;
        #pragma unroll
        for (int s = 0; s < 8; s++) {
            unsigned long long x = q8[s];
            #pragma unroll
            for (int k = 0; k < 8; k++)
                w |= ((x >> (8 * k)) & 1ULL) << (8 * s + k);
        }
        bool diff = (w != g_est[rbuf][tid][f][jd]);
        g_est[wbuf][tid][f][jd] = w;
        unsigned bal = __ballot_sync(0xffffffffu, diff);
        if (lane == 0 && bal) atomicOr(&g_diff[t], 1);
    }
}

// ---------------- final similarity (cleanup) ----------------
__global__ void k_sim_final() {
    int f = blockIdx.x;
    int m = blockIdx.y * 256 + threadIdx.x;
    int b0 = blockIdx.z * 8;
    __shared__ unsigned long long sh[8][WPD];
    if (threadIdx.x < 128) {
        int bb = threadIdx.x >> 4, j = threadIdx.x & 15;
        sh[bb][j] = g_est[FINAL_BUF][b0 + bb][f][j];
    }
    __syncthreads();
    int acc[8];
    #pragma unroll
    for (int i = 0; i < 8; i++) acc[i] = 0;
    #pragma unroll
    for (int j = 0; j < WPD; j++) {
        unsigned long long w = g_cb_bits[f][j][m];
        #pragma unroll
        for (int bb = 0; bb < 8; bb++) acc[bb] += __popcll(w ^ sh[bb][j]);
    }
    #pragma unroll
    for (int bb = 0; bb < 8; bb++)
        g_sim[f][b0 + bb][m] = __int2half_rn(D - 2 * acc[bb]);
}

// ---------------- output kernels ----------------
__global__ void k_argmax(float* __restrict__ out) {
    int bf = blockIdx.x;
    int b = bf >> 2, f = bf & 3;
    const __half* s = g_sim[f][b];
    int best = -1;
    #pragma unroll
    for (int i = 0; i < 16; i++) {
        int m = threadIdx.x + i * 256;
        int v = (int)__half2float(s[m]);
        int a = v < 0 ? -v : v;
        int key = (a << 12) | (4095 - m);   // max abs, then lowest m
        if (key > best) best = key;
    }
    __shared__ int sh[256];
    sh[threadIdx.x] = best;
    __syncthreads();
    for (int step = 128; step > 0; step >>= 1) {
        if (threadIdx.x < step) {
            if (sh[threadIdx.x + step] > sh[threadIdx.x])
                sh[threadIdx.x] = sh[threadIdx.x + step];
        }
        __syncthreads();
    }
    if (threadIdx.x == 0)
        out[bf] = (float)(4095 - (sh[0] & 4095));
}

__global__ void k_est_out(float* __restrict__ out) {
    int idx = blockIdx.x * 256 + threadIdx.x;   // b*F*D + f*D + d
    int d = idx & (D - 1);
    int f = (idx >> 10) & 3;
    int b = idx >> 12;
    unsigned long long w = g_est[FINAL_BUF][b][f][d >> 6];
    out[idx] = ((w >> (d & 63)) & 1ULL) ? -1.f : 1.f;
}

__global__ void k_misc(float* __restrict__ out) {
    int iters = ITERS, conv = 0;
    for (int t = 0; t < ITERS; t++) {
        if (g_diff[t] == 0) { iters = t + 1; conv = 1; break; }
    }
    out[0] = (float)iters;
    out[1] = (float)conv;
}

// ---------------- launcher ----------------
extern "C" void kernel_launch(void* const* d_in, const int* in_sizes, int n_in,
                              void* d_out, int out_size) {
    const float* input = nullptr;
    const float* est0  = nullptr;
    const float* cb    = nullptr;
    for (int i = 0; i < n_in; i++) {
        if      (in_sizes[i] == B * D)     input = (const float*)d_in[i];
        else if (in_sizes[i] == B * F * D) est0  = (const float*)d_in[i];
        else if (in_sizes[i] == F * M * D) cb    = (const float*)d_in[i];
    }
    if (!input) input = (const float*)d_in[0];
    if (!est0)  est0  = (const float*)d_in[1];
    if (!cb)    cb    = (const float*)d_in[2];
    float* out = (float*)d_out;

    k_pack_small<<<(B * WPD + B * F * WPD + ITERS + 255) / 256, 256>>>(input, est0);
    k_pack_cb<<<F * WPD * M / 256, 256>>>(cb);
    k_pack_cbcol<<<F * WPM * D / 256, 256>>>(cb);
    k_gram<<<dim3(F, D / 32, D / 32), 256>>>();

    for (int t = 0; t < ITERS; t++) {
        k_iter<<<dim3(F, D / 64), 256>>>(t);
    }

    k_sim_final<<<dim3(F, M / 256, B / 8), 256>>>();

    // output layout (float32): order (outcome, est, iters, conv)
    const long long n_out = B * F;                 // 256
    const long long n_est = (long long)B * F * D;  // 262144
    long long off_outcome = -1, off_est = -1, off_misc = -1;
    if ((long long)out_size >= n_out + n_est + 2) {
        off_outcome = 0; off_est = n_out; off_misc = n_out + n_est;
    } else if ((long long)out_size == n_est) {
        off_est = 0;
    } else if ((long long)out_size == n_out) {
        off_outcome = 0;
    } else if ((long long)out_size == n_out + n_est) {
        off_outcome = 0; off_est = n_out;
    } else {
        off_outcome = 0;
    }

    if (off_outcome >= 0) k_argmax<<<B * F, 256>>>(out + off_outcome);
    if (off_est     >= 0) k_est_out<<<(B * F * D) / 256, 256>>>(out + off_est);
    if (off_misc    >= 0) k_misc<<<1, 1>>>(out + off_misc);
}

// round 4
// speedup vs baseline: 5.2315x; 1.0325x over previous
#include <cuda_runtime.h>
#include <cuda_fp16.h>
#include <cstdint>

#define B 64
#define F 4
#define M 4096
#define D 1024
#define ITERS 15
#define WPD 16   // 64-bit words per D-dim vector
#define WPM 64   // 64-bit words per M-dim vector
#define FINAL_BUF (ITERS & 1)

// ---------------- device scratch (no allocs allowed) ----------------
__device__ unsigned long long g_cb_bits[F][WPD][M];   // codebook bits over d, [f][word][m] (2 MB)
__device__ unsigned long long g_cbcol[F][D][WPM];     // codebook bits over m, [f][d][word] (2 MB)
__device__ __half             g_G[F][D][D];           // Gram matrix C^T C, exact even ints (8 MB)
__device__ unsigned long long g_in_bits[B][WPD];
__device__ unsigned long long g_est[2][B][F][WPD];    // double-buffered estimates (bit 1 = -1)
__device__ __half             g_sim[F][B][M];         // final similarity (exact ints in fp16)
__device__ int                g_diff[ITERS];          // per-iteration "changed" flags

// ---------------- helpers ----------------
__device__ __forceinline__ unsigned long long pack64(const float* p) {
    unsigned long long w = 0ULL;
    #pragma unroll
    for (int t = 0; t < 16; t++) {
        float4 v = reinterpret_cast<const float4*>(p)[t];
        w |= ((unsigned long long)(v.x < 0.f)) << (4 * t + 0);
        w |= ((unsigned long long)(v.y < 0.f)) << (4 * t + 1);
        w |= ((unsigned long long)(v.z < 0.f)) << (4 * t + 2);
        w |= ((unsigned long long)(v.w < 0.f)) << (4 * t + 3);
    }
    return w;
}

__device__ __forceinline__ void mma16816(float* c,
                                         unsigned a0, unsigned a1, unsigned a2, unsigned a3,
                                         unsigned b0, unsigned b1) {
    asm volatile(
        "mma.sync.aligned.m16n8k16.row.col.f32.f16.f16.f32 "
        "{%0,%1,%2,%3}, {%4,%5,%6,%7}, {%8,%9}, {%0,%1,%2,%3};"
        : "+f"(c[0]), "+f"(c[1]), "+f"(c[2]), "+f"(c[3])
        : "r"(a0), "r"(a1), "r"(a2), "r"(a3), "r"(b0), "r"(b1));
}

// bits (2 low bits, 1 = negative) -> packed half2 {+-1, +-1}
__device__ __forceinline__ unsigned bits2h2(unsigned bits) {
    return 0x3C003C00u ^ ((bits & 1u) << 15) ^ ((bits & 2u) << 30);
}

// ---------------- packing kernels ----------------
__global__ void k_pack_small(const float* __restrict__ input,
                             const float* __restrict__ est0) {
    int idx = blockIdx.x * 256 + threadIdx.x;
    if (idx < B * WPD) {
        int b = idx >> 4, j = idx & 15;
        g_in_bits[b][j] = pack64(input + b * D + j * 64);
    } else if (idx < B * WPD + B * F * WPD) {
        int w = idx - B * WPD;
        int b = w >> 6, f = (w >> 4) & 3, j = w & 15;
        g_est[0][b][f][j] = pack64(est0 + (size_t)(b * F + f) * D + j * 64);
    } else if (idx < B * WPD + B * F * WPD + ITERS) {
        g_diff[idx - (B * WPD + B * F * WPD)] = 0;
    }
}

__global__ void k_pack_cb(const float* __restrict__ cb) {
    int idx = blockIdx.x * 256 + threadIdx.x;   // F*WPD*M total
    int m = idx & (M - 1);
    int j = (idx >> 12) & 15;
    int f = idx >> 16;
    g_cb_bits[f][j][m] = pack64(cb + ((size_t)(f * M + m)) * D + j * 64);
}

// bits over m for each (f, d): g_cbcol[f][d][j], bit k <-> m = j*64+k
__global__ void k_pack_cbcol(const float* __restrict__ cb) {
    int idx = blockIdx.x * 256 + threadIdx.x;   // (f*WPM + j)*D + d
    int d = idx & (D - 1);
    int rest = idx >> 10;
    int j = rest & 63;
    int f = rest >> 6;
    const float* base = cb + ((size_t)f * M + (size_t)j * 64) * D + d;
    unsigned long long w = 0ULL;
    #pragma unroll
    for (int k = 0; k < 64; k++) {
        float v = base[(size_t)k * D];
        w |= ((unsigned long long)(v < 0.f)) << k;
    }
    g_cbcol[f][d][j] = w;
}

// ---------------- Gram matrix: G[f][a][b] = dot(col_a, col_b) = M - 2*popc ----------------
__global__ void __launch_bounds__(256) k_gram() {
    __shared__ unsigned long long shX[32][WPM + 1];
    __shared__ unsigned long long shY[32][WPM + 1];
    int f  = blockIdx.x;
    int x0 = blockIdx.y * 32;
    int y0 = blockIdx.z * 32;
    int tid = threadIdx.x;
    #pragma unroll
    for (int r = 0; r < 8; r++) {
        int w = tid + 256 * r;
        int row = w >> 6, col = w & 63;
        shX[row][col] = g_cbcol[f][x0 + row][col];
        shY[row][col] = g_cbcol[f][y0 + row][col];
    }
    __syncthreads();
    int x  = tid >> 3;
    int y4 = (tid & 7) * 4;
    int acc0 = 0, acc1 = 0, acc2 = 0, acc3 = 0;
    #pragma unroll
    for (int w = 0; w < WPM; w++) {
        unsigned long long xv = shX[x][w];
        acc0 += __popcll(xv ^ shY[y4 + 0][w]);
        acc1 += __popcll(xv ^ shY[y4 + 1][w]);
        acc2 += __popcll(xv ^ shY[y4 + 2][w]);
        acc3 += __popcll(xv ^ shY[y4 + 3][w]);
    }
    g_G[f][x0 + x][y0 + y4 + 0] = __int2half_rn(M - 2 * acc0);
    g_G[f][x0 + x][y0 + y4 + 1] = __int2half_rn(M - 2 * acc1);
    g_G[f][x0 + x][y0 + y4 + 2] = __int2half_rn(M - 2 * acc2);
    g_G[f][x0 + x][y0 + y4 + 3] = __int2half_rn(M - 2 * acc3);
}

// ---------------- fused iteration kernel ----------------
// upd = sign(new_est @ G[f]), pack to bits, diff flag, double-buffered est.
// grid = (F, D/64), block = 256 (8 warps). Block tile: 64(B) x 64(d), K = D.
__global__ void __launch_bounds__(256) k_iter(int t) {
    const int rbuf = t & 1, wbuf = (t & 1) ^ 1;
    __shared__ unsigned long long snew[64][WPD + 1];   // new_est bits, this f
    __shared__ __align__(16) __half shB[64][72];       // G chunk [d][k]
    __shared__ unsigned char sbytes[64][64];           // sign bytes

    int f  = blockIdx.x;
    int jd = blockIdx.y;           // word index == d-tile (64 d per word)
    int tid = threadIdx.x;
    int wid = tid >> 5, lane = tid & 31, g = lane >> 2, q = lane & 3;
    int mrow0 = (wid >> 1) * 16;   // 4 row groups of 16
    int ncol0 = (wid & 1) * 32;    // 2 col groups of 32

    // new_est bits: in ^ (xor over all f) ^ est_f
    #pragma unroll
    for (int r = 0; r < 4; r++) {
        int idx = tid + 256 * r;   // 1024 words
        int b = idx >> 4, j = idx & 15;
        unsigned long long tot = g_in_bits[b][j];
        #pragma unroll
        for (int ff = 0; ff < F; ff++) tot ^= g_est[rbuf][b][ff][j];
        snew[b][j] = tot ^ g_est[rbuf][b][f][j];
    }
    __syncthreads();

    float acc[4][4];
    #pragma unroll
    for (int i = 0; i < 4; i++)
        #pragma unroll
        for (int jj = 0; jj < 4; jj++) acc[i][jj] = 0.f;

    const int d0 = jd * 64;
    for (int kc = 0; kc < D; kc += 64) {
        // load G chunk: 64 rows (d) x 64 halves (k) = 512 uint4, 2 per thread
        #pragma unroll
        for (int r = 0; r < 2; r++) {
            int idx = tid + 256 * r;
            int row = idx >> 3, seg = idx & 7;
            *(uint4*)&shB[row][seg * 8] =
                *(const uint4*)&g_G[f][d0 + row][kc + seg * 8];
        }
        __syncthreads();
        unsigned long long w0 = snew[mrow0 + g][kc >> 6];
        unsigned long long w1 = snew[mrow0 + 8 + g][kc >> 6];
        #pragma unroll
        for (int kk = 0; kk < 64; kk += 16) {
            unsigned a0 = bits2h2((unsigned)(w0 >> (kk + q * 2)) & 3u);
            unsigned a1 = bits2h2((unsigned)(w1 >> (kk + q * 2)) & 3u);
            unsigned a2 = bits2h2((unsigned)(w0 >> (kk + 8 + q * 2)) & 3u);
            unsigned a3 = bits2h2((unsigned)(w1 >> (kk + 8 + q * 2)) & 3u);
            #pragma unroll
            for (int nt = 0; nt < 4; nt++) {
                unsigned b0v = *(const unsigned*)&shB[ncol0 + nt * 8 + g][kk + q * 2];
                unsigned b1v = *(const unsigned*)&shB[ncol0 + nt * 8 + g][kk + 8 + q * 2];
                mma16816(acc[nt], a0, a1, a2, a3, b0v, b1v);
            }
        }
        __syncthreads();
    }

    // epilogue: sign bytes -> smem
    int r0 = mrow0 + g;
    #pragma unroll
    for (int nt = 0; nt < 4; nt++) {
        int c0 = ncol0 + nt * 8 + q * 2;
        sbytes[r0    ][c0    ] = (unsigned char)(acc[nt][0] < 0.f);
        sbytes[r0    ][c0 + 1] = (unsigned char)(acc[nt][1] < 0.f);
        sbytes[r0 + 8][c0    ] = (unsigned char)(acc[nt][2] < 0.f);
        sbytes[r0 + 8][c0 + 1] = (unsigned char)(acc[nt][3] < 0.f);
    }
    __syncthreads();

    if (tid < 64) {
        const unsigned long long* q8 = (const unsigned long long*)sbytes[tid];
        unsigned long long w = 0ULL;
        #pragma unroll
        for (int s = 0; s < 8; s++) {
            unsigned long long x = q8[s];
            #pragma unroll
            for (int k = 0; k < 8; k++)
                w |= ((x >> (8 * k)) & 1ULL) << (8 * s + k);
        }
        bool diff = (w != g_est[rbuf][tid][f][jd]);
        g_est[wbuf][tid][f][jd] = w;
        unsigned bal = __ballot_sync(0xffffffffu, diff);
        if (lane == 0 && bal) atomicOr(&g_diff[t], 1);
    }
}

// ---------------- final similarity (cleanup) ----------------
__global__ void k_sim_final() {
    int f = blockIdx.x;
    int m = blockIdx.y * 256 + threadIdx.x;
    int b0 = blockIdx.z * 8;
    __shared__ unsigned long long sh[8][WPD];
    if (threadIdx.x < 128) {
        int bb = threadIdx.x >> 4, j = threadIdx.x & 15;
        sh[bb][j] = g_est[FINAL_BUF][b0 + bb][f][j];
    }
    __syncthreads();
    int acc[8];
    #pragma unroll
    for (int i = 0; i < 8; i++) acc[i] = 0;
    #pragma unroll
    for (int j = 0; j < WPD; j++) {
        unsigned long long w = g_cb_bits[f][j][m];
        #pragma unroll
        for (int bb = 0; bb < 8; bb++) acc[bb] += __popcll(w ^ sh[bb][j]);
    }
    #pragma unroll
    for (int bb = 0; bb < 8; bb++)
        g_sim[f][b0 + bb][m] = __int2half_rn(D - 2 * acc[bb]);
}

// ---------------- output kernels ----------------
__global__ void k_argmax(float* __restrict__ out) {
    int bf = blockIdx.x;
    int b = bf >> 2, f = bf & 3;
    const __half* s = g_sim[f][b];
    int best = -1;
    #pragma unroll
    for (int i = 0; i < 16; i++) {
        int m = threadIdx.x + i * 256;
        int v = (int)__half2float(s[m]);
        int a = v < 0 ? -v : v;
        int key = (a << 12) | (4095 - m);   // max abs, then lowest m
        if (key > best) best = key;
    }
    __shared__ int sh[256];
    sh[threadIdx.x] = best;
    __syncthreads();
    for (int step = 128; step > 0; step >>= 1) {
        if (threadIdx.x < step) {
            if (sh[threadIdx.x + step] > sh[threadIdx.x])
                sh[threadIdx.x] = sh[threadIdx.x + step];
        }
        __syncthreads();
    }
    if (threadIdx.x == 0)
        out[bf] = (float)(4095 - (sh[0] & 4095));
}

__global__ void k_est_out(float* __restrict__ out) {
    int idx = blockIdx.x * 256 + threadIdx.x;   // b*F*D + f*D + d
    int d = idx & (D - 1);
    int f = (idx >> 10) & 3;
    int b = idx >> 12;
    unsigned long long w = g_est[FINAL_BUF][b][f][d >> 6];
    out[idx] = ((w >> (d & 63)) & 1ULL) ? -1.f : 1.f;
}

__global__ void k_misc(float* __restrict__ out) {
    int iters = ITERS, conv = 0;
    for (int t = 0; t < ITERS; t++) {
        if (g_diff[t] == 0) { iters = t + 1; conv = 1; break; }
    }
    out[0] = (float)iters;
    out[1] = (float)conv;
}

// ---------------- launcher ----------------
extern "C" void kernel_launch(void* const* d_in, const int* in_sizes, int n_in,
                              void* d_out, int out_size) {
    const float* input = nullptr;
    const float* est0  = nullptr;
    const float* cb    = nullptr;
    for (int i = 0; i < n_in; i++) {
        if      (in_sizes[i] == B * D)     input = (const float*)d_in[i];
        else if (in_sizes[i] == B * F * D) est0  = (const float*)d_in[i];
        else if (in_sizes[i] == F * M * D) cb    = (const float*)d_in[i];
    }
    if (!input) input = (const float*)d_in[0];
    if (!est0)  est0  = (const float*)d_in[1];
    if (!cb)    cb    = (const float*)d_in[2];
    float* out = (float*)d_out;

    k_pack_small<<<(B * WPD + B * F * WPD + ITERS + 255) / 256, 256>>>(input, est0);
    k_pack_cb<<<F * WPD * M / 256, 256>>>(cb);
    k_pack_cbcol<<<F * WPM * D / 256, 256>>>(cb);
    k_gram<<<dim3(F, D / 32, D / 32), 256>>>();

    for (int t = 0; t < ITERS; t++) {
        k_iter<<<dim3(F, D / 64), 256>>>(t);
    }

    k_sim_final<<<dim3(F, M / 256, B / 8), 256>>>();

    // output layout (float32): order (outcome, est, iters, conv)
    const long long n_out = B * F;                 // 256
    const long long n_est = (long long)B * F * D;  // 262144
    long long off_outcome = -1, off_est = -1, off_misc = -1;
    if ((long long)out_size >= n_out + n_est + 2) {
        off_outcome = 0; off_est = n_out; off_misc = n_out + n_est;
    } else if ((long long)out_size == n_est) {
        off_est = 0;
    } else if ((long long)out_size == n_out) {
        off_outcome = 0;
    } else if ((long long)out_size == n_out + n_est) {
        off_outcome = 0; off_est = n_out;
    } else {
        off_outcome = 0;
    }

    if (off_outcome >= 0) k_argmax<<<B * F, 256>>>(out + off_outcome);
    if (off_est     >= 0) k_est_out<<<(B * F * D) / 256, 256>>>(out + off_est);
    if (off_misc    >= 0) k_misc<<<1, 1>>>(out + off_misc);
}

// round 5
// speedup vs baseline: 6.6664x; 1.2743x over previous
#include <cuda_runtime.h>
#include <cuda_fp16.h>
#include <cstdint>

#define B 64
#define F 4
#define M 4096
#define D 1024
#define ITERS 15
#define WPD 16   // 64-bit words per D-dim vector
#define WPM 64   // 64-bit words per M-dim vector
#define FINAL_BUF (ITERS & 1)

// ---------------- device scratch (no allocs allowed) ----------------
__device__ unsigned long long g_cb_bits[F][WPD][M];   // codebook bits over d, [f][word][m] (2 MB)
__device__ unsigned long long g_cbcol[F][D][WPM];     // codebook bits over m, [f][d][word] (2 MB)
__device__ __half             g_G[F][D][D];           // Gram matrix C^T C, exact even ints (8 MB)
__device__ unsigned long long g_in_bits[B][WPD];
__device__ unsigned long long g_est[2][B][F][WPD];    // double-buffered estimates (bit 1 = -1)
__device__ int                g_key[B * F];           // argmax keys (atomicMax)
__device__ int                g_diff[ITERS];          // per-iteration "changed" flags

// ---------------- helpers ----------------
__device__ __forceinline__ unsigned long long pack64(const float* p) {
    unsigned long long w = 0ULL;
    #pragma unroll
    for (int t = 0; t < 16; t++) {
        float4 v = reinterpret_cast<const float4*>(p)[t];
        w |= ((unsigned long long)(v.x < 0.f)) << (4 * t + 0);
        w |= ((unsigned long long)(v.y < 0.f)) << (4 * t + 1);
        w |= ((unsigned long long)(v.z < 0.f)) << (4 * t + 2);
        w |= ((unsigned long long)(v.w < 0.f)) << (4 * t + 3);
    }
    return w;
}

__device__ __forceinline__ void mma16816(float* c,
                                         unsigned a0, unsigned a1, unsigned a2, unsigned a3,
                                         unsigned b0, unsigned b1) {
    asm volatile(
        "mma.sync.aligned.m16n8k16.row.col.f32.f16.f16.f32 "
        "{%0,%1,%2,%3}, {%4,%5,%6,%7}, {%8,%9}, {%0,%1,%2,%3};"
        : "+f"(c[0]), "+f"(c[1]), "+f"(c[2]), "+f"(c[3])
        : "r"(a0), "r"(a1), "r"(a2), "r"(a3), "r"(b0), "r"(b1));
}

// bits (2 low bits, 1 = negative) -> packed half2 {+-1, +-1}
__device__ __forceinline__ unsigned bits2h2(unsigned bits) {
    return 0x3C003C00u ^ ((bits & 1u) << 15) ^ ((bits & 2u) << 30);
}

// ---------------- packing kernels ----------------
__global__ void k_pack_small(const float* __restrict__ input,
                             const float* __restrict__ est0) {
    int idx = blockIdx.x * 256 + threadIdx.x;
    const int base = B * WPD + B * F * WPD;
    if (idx < B * WPD) {
        int b = idx >> 4, j = idx & 15;
        g_in_bits[b][j] = pack64(input + b * D + j * 64);
    } else if (idx < base) {
        int w = idx - B * WPD;
        int b = w >> 6, f = (w >> 4) & 3, j = w & 15;
        g_est[0][b][f][j] = pack64(est0 + (size_t)(b * F + f) * D + j * 64);
    } else if (idx < base + ITERS) {
        g_diff[idx - base] = 0;
    } else if (idx < base + ITERS + B * F) {
        g_key[idx - base - ITERS] = -1;
    }
}

__global__ void k_pack_cb(const float* __restrict__ cb) {
    int idx = blockIdx.x * 256 + threadIdx.x;   // F*WPD*M total
    int m = idx & (M - 1);
    int j = (idx >> 12) & 15;
    int f = idx >> 16;
    g_cb_bits[f][j][m] = pack64(cb + ((size_t)(f * M + m)) * D + j * 64);
}

// bits over m for each (f, d): g_cbcol[f][d][j], bit k <-> m = j*64+k
__global__ void k_pack_cbcol(const float* __restrict__ cb) {
    int idx = blockIdx.x * 256 + threadIdx.x;   // (f*WPM + j)*D + d
    int d = idx & (D - 1);
    int rest = idx >> 10;
    int j = rest & 63;
    int f = rest >> 6;
    const float* base = cb + ((size_t)f * M + (size_t)j * 64) * D + d;
    unsigned long long w = 0ULL;
    #pragma unroll
    for (int k = 0; k < 64; k++) {
        float v = base[(size_t)k * D];
        w |= ((unsigned long long)(v < 0.f)) << k;
    }
    g_cbcol[f][d][j] = w;
}

// ---------------- Gram: symmetric, 64x64 tiles, 4x4 per thread ----------------
__global__ void __launch_bounds__(256) k_gram2() {
    __shared__ unsigned long long shX[64][19];   // padded: conflict-free strided reads
    __shared__ unsigned long long shY[64][19];
    __shared__ __half stage[64][72];

    int f = blockIdx.x;
    int p = blockIdx.y;                 // triangular pair index, 136 per f
    int tx = 0;
    while (p >= 16 - tx) { p -= 16 - tx; tx++; }
    int ty = tx + p;
    int x0 = tx * 64, y0 = ty * 64;

    int tid = threadIdx.x;
    int u = (tid >> 4) * 4;             // x sub-row (0..60)
    int v = (tid & 15) * 4;             // y sub-row (0..60)

    int acc[4][4];
    #pragma unroll
    for (int i = 0; i < 4; i++)
        #pragma unroll
        for (int j = 0; j < 4; j++) acc[i][j] = 0;

    for (int kc = 0; kc < WPM; kc += 16) {
        #pragma unroll
        for (int r = 0; r < 4; r++) {
            int idx = tid + 256 * r;    // 1024 words
            int row = idx >> 4, w = idx & 15;
            shX[row][w] = g_cbcol[f][x0 + row][kc + w];
            shY[row][w] = g_cbcol[f][y0 + row][kc + w];
        }
        __syncthreads();
        #pragma unroll
        for (int w = 0; w < 16; w++) {
            unsigned long long x0v = shX[u    ][w];
            unsigned long long x1v = shX[u + 1][w];
            unsigned long long x2v = shX[u + 2][w];
            unsigned long long x3v = shX[u + 3][w];
            unsigned long long y0v = shY[v    ][w];
            unsigned long long y1v = shY[v + 1][w];
            unsigned long long y2v = shY[v + 2][w];
            unsigned long long y3v = shY[v + 3][w];
            acc[0][0] += __popcll(x0v ^ y0v); acc[0][1] += __popcll(x0v ^ y1v);
            acc[0][2] += __popcll(x0v ^ y2v); acc[0][3] += __popcll(x0v ^ y3v);
            acc[1][0] += __popcll(x1v ^ y0v); acc[1][1] += __popcll(x1v ^ y1v);
            acc[1][2] += __popcll(x1v ^ y2v); acc[1][3] += __popcll(x1v ^ y3v);
            acc[2][0] += __popcll(x2v ^ y0v); acc[2][1] += __popcll(x2v ^ y1v);
            acc[2][2] += __popcll(x2v ^ y2v); acc[2][3] += __popcll(x2v ^ y3v);
            acc[3][0] += __popcll(x3v ^ y0v); acc[3][1] += __popcll(x3v ^ y1v);
            acc[3][2] += __popcll(x3v ^ y2v); acc[3][3] += __popcll(x3v ^ y3v);
        }
        __syncthreads();
    }

    // stage tile (rows = x, cols = y)
    #pragma unroll
    for (int i = 0; i < 4; i++)
        #pragma unroll
        for (int j = 0; j < 4; j++)
            stage[u + i][v + j] = __int2half_rn(M - 2 * acc[i][j]);
    __syncthreads();

    // pass 1: G[x0+row][y0+col], coalesced
    #pragma unroll
    for (int r = 0; r < 2; r++) {
        int idx = tid + 256 * r;        // 512 uint4
        int row = idx >> 3, seg = idx & 7;
        *(uint4*)&g_G[f][x0 + row][y0 + seg * 8] = *(const uint4*)&stage[row][seg * 8];
    }

    // pass 2: transposed G[y0+r][x0+..] (skip for diagonal tiles)
    if (tx != ty) {
        int r = tid >> 2, qd = tid & 3;     // r: 0..63, qd: 0..3 (16-col quarters)
        unsigned wds[8];
        #pragma unroll
        for (int k = 0; k < 8; k++) {
            unsigned short h0 = __half_as_ushort(stage[qd * 16 + 2 * k    ][r]);
            unsigned short h1 = __half_as_ushort(stage[qd * 16 + 2 * k + 1][r]);
            wds[k] = ((unsigned)h1 << 16) | h0;
        }
        uint4 lo = make_uint4(wds[0], wds[1], wds[2], wds[3]);
        uint4 hi = make_uint4(wds[4], wds[5], wds[6], wds[7]);
        *(uint4*)&g_G[f][y0 + r][x0 + qd * 16    ] = lo;
        *(uint4*)&g_G[f][y0 + r][x0 + qd * 16 + 8] = hi;
    }
}

// ---------------- fused iteration kernel ----------------
// upd = sign(new_est @ G[f]), pack to bits, diff flag, double-buffered est.
// grid = (F, 16, 2), block = 256 (8 warps). Block tile: 32(B) x 64(d), K = D.
__global__ void __launch_bounds__(256) k_iter(int t) {
    const int rbuf = t & 1, wbuf = (t & 1) ^ 1;
    __shared__ unsigned long long snew[32][WPD + 1];   // new_est bits, this f / b-half
    __shared__ __align__(16) __half shB[64][72];       // G chunk [d][k]
    __shared__ unsigned char sbytes[32][64];           // sign bytes

    int f  = blockIdx.x;
    int jd = blockIdx.y;               // d-tile (64 d per word)
    int b0 = blockIdx.z * 32;          // batch half
    int tid = threadIdx.x;
    int wid = tid >> 5, lane = tid & 31, g = lane >> 2, q = lane & 3;
    int mrow0 = (wid >> 2) * 16;       // 2 row groups of 16
    int ncol0 = (wid & 3) * 16;        // 4 col groups of 16

    // new_est bits: in ^ (xor over all f) ^ est_f, 512 words
    #pragma unroll
    for (int r = 0; r < 2; r++) {
        int idx = tid + 256 * r;
        int bl = idx >> 4, j = idx & 15;
        int b = b0 + bl;
        unsigned long long tot = g_in_bits[b][j];
        #pragma unroll
        for (int ff = 0; ff < F; ff++) tot ^= g_est[rbuf][b][ff][j];
        snew[bl][j] = tot ^ g_est[rbuf][b][f][j];
    }
    __syncthreads();

    float acc[2][4];
    #pragma unroll
    for (int i = 0; i < 2; i++)
        #pragma unroll
        for (int jj = 0; jj < 4; jj++) acc[i][jj] = 0.f;

    const int d0 = jd * 64;
    for (int kc = 0; kc < D; kc += 64) {
        // load G chunk: 64 rows (d) x 64 halves (k) = 512 uint4, 2 per thread
        #pragma unroll
        for (int r = 0; r < 2; r++) {
            int idx = tid + 256 * r;
            int row = idx >> 3, seg = idx & 7;
            *(uint4*)&shB[row][seg * 8] =
                *(const uint4*)&g_G[f][d0 + row][kc + seg * 8];
        }
        __syncthreads();
        unsigned long long w0 = snew[mrow0 + g][kc >> 6];
        unsigned long long w1 = snew[mrow0 + 8 + g][kc >> 6];
        #pragma unroll
        for (int kk = 0; kk < 64; kk += 16) {
            unsigned a0 = bits2h2((unsigned)(w0 >> (kk + q * 2)) & 3u);
            unsigned a1 = bits2h2((unsigned)(w1 >> (kk + q * 2)) & 3u);
            unsigned a2 = bits2h2((unsigned)(w0 >> (kk + 8 + q * 2)) & 3u);
            unsigned a3 = bits2h2((unsigned)(w1 >> (kk + 8 + q * 2)) & 3u);
            #pragma unroll
            for (int nt = 0; nt < 2; nt++) {
                unsigned b0v = *(const unsigned*)&shB[ncol0 + nt * 8 + g][kk + q * 2];
                unsigned b1v = *(const unsigned*)&shB[ncol0 + nt * 8 + g][kk + 8 + q * 2];
                mma16816(acc[nt], a0, a1, a2, a3, b0v, b1v);
            }
        }
        __syncthreads();
    }

    // epilogue: sign bytes -> smem
    int r0 = mrow0 + g;
    #pragma unroll
    for (int nt = 0; nt < 2; nt++) {
        int c0 = ncol0 + nt * 8 + q * 2;
        sbytes[r0    ][c0    ] = (unsigned char)(acc[nt][0] < 0.f);
        sbytes[r0    ][c0 + 1] = (unsigned char)(acc[nt][1] < 0.f);
        sbytes[r0 + 8][c0    ] = (unsigned char)(acc[nt][2] < 0.f);
        sbytes[r0 + 8][c0 + 1] = (unsigned char)(acc[nt][3] < 0.f);
    }
    __syncthreads();

    if (tid < 32) {
        const unsigned long long* q8 = (const unsigned long long*)sbytes[tid];
        unsigned long long w = 0ULL;
        #pragma unroll
        for (int s = 0; s < 8; s++) {
            unsigned long long x = q8[s];
            #pragma unroll
            for (int k = 0; k < 8; k++)
                w |= ((x >> (8 * k)) & 1ULL) << (8 * s + k);
        }
        int b = b0 + tid;
        bool diff = (w != g_est[rbuf][b][f][jd]);
        g_est[wbuf][b][f][jd] = w;
        unsigned bal = __ballot_sync(0xffffffffu, diff);
        if (lane == 0 && bal) atomicOr(&g_diff[t], 1);
    }
}

// ---------------- cleanup: partial argmax over m-chunks via atomicMax ----------------
// grid = (F, M/256, B/8), block = 256
__global__ void k_cleanup() {
    int f = blockIdx.x;
    int m = blockIdx.y * 256 + threadIdx.x;
    int b0 = blockIdx.z * 8;
    __shared__ unsigned long long sh[8][WPD];
    __shared__ int skey[8][33];
    if (threadIdx.x < 128) {
        int bb = threadIdx.x >> 4, j = threadIdx.x & 15;
        sh[bb][j] = g_est[FINAL_BUF][b0 + bb][f][j];
    }
    __syncthreads();
    int acc[8];
    #pragma unroll
    for (int i = 0; i < 8; i++) acc[i] = 0;
    #pragma unroll
    for (int j = 0; j < WPD; j++) {
        unsigned long long w = g_cb_bits[f][j][m];
        #pragma unroll
        for (int bb = 0; bb < 8; bb++) acc[bb] += __popcll(w ^ sh[bb][j]);
    }
    // per-thread keys, warp-reduce, then atomicMax per (b,f)
    int lane = threadIdx.x & 31, wid = threadIdx.x >> 5;
    #pragma unroll
    for (int bb = 0; bb < 8; bb++) {
        int vv = D - 2 * acc[bb];
        int a = vv < 0 ? -vv : vv;
        int key = (a << 12) | (4095 - m);
        #pragma unroll
        for (int s = 16; s > 0; s >>= 1) {
            int o = __shfl_down_sync(0xffffffffu, key, s);
            if (o > key) key = o;
        }
        if (lane == 0) skey[bb][wid] = key;
    }
    __syncthreads();
    if (threadIdx.x < 8) {
        int bb = threadIdx.x;
        int best = skey[bb][0];
        #pragma unroll
        for (int w2 = 1; w2 < 8; w2++)
            if (skey[bb][w2] > best) best = skey[bb][w2];
        atomicMax(&g_key[(b0 + bb) * F + f], best);
    }
}

// ---------------- combined output kernel ----------------
__global__ void k_out(float* __restrict__ out_outcome,
                      float* __restrict__ out_est,
                      float* __restrict__ out_misc) {
    int idx = blockIdx.x * 256 + threadIdx.x;   // est: b*F*D + f*D + d
    if (out_est) {
        int d = idx & (D - 1);
        int f = (idx >> 10) & 3;
        int b = idx >> 12;
        unsigned long long w = g_est[FINAL_BUF][b][f][d >> 6];
        out_est[idx] = ((w >> (d & 63)) & 1ULL) ? -1.f : 1.f;
    }
    if (blockIdx.x == 0) {
        if (out_outcome && threadIdx.x < B * F)
            out_outcome[threadIdx.x] = (float)(4095 - (g_key[threadIdx.x] & 4095));
        if (out_misc && threadIdx.x == 0) {
            int iters = ITERS, conv = 0;
            for (int t = 0; t < ITERS; t++) {
                if (g_diff[t] == 0) { iters = t + 1; conv = 1; break; }
            }
            out_misc[0] = (float)iters;
            out_misc[1] = (float)conv;
        }
    }
}

// ---------------- launcher ----------------
extern "C" void kernel_launch(void* const* d_in, const int* in_sizes, int n_in,
                              void* d_out, int out_size) {
    const float* input = nullptr;
    const float* est0  = nullptr;
    const float* cb    = nullptr;
    for (int i = 0; i < n_in; i++) {
        if      (in_sizes[i] == B * D)     input = (const float*)d_in[i];
        else if (in_sizes[i] == B * F * D) est0  = (const float*)d_in[i];
        else if (in_sizes[i] == F * M * D) cb    = (const float*)d_in[i];
    }
    if (!input) input = (const float*)d_in[0];
    if (!est0)  est0  = (const float*)d_in[1];
    if (!cb)    cb    = (const float*)d_in[2];
    float* out = (float*)d_out;

    const int n_small = B * WPD + B * F * WPD + ITERS + B * F;
    k_pack_small<<<(n_small + 255) / 256, 256>>>(input, est0);
    k_pack_cb<<<F * WPD * M / 256, 256>>>(cb);
    k_pack_cbcol<<<F * WPM * D / 256, 256>>>(cb);
    k_gram2<<<dim3(F, 136), 256>>>();

    for (int t = 0; t < ITERS; t++) {
        k_iter<<<dim3(F, D / 64, 2), 256>>>(t);
    }

    k_cleanup<<<dim3(F, M / 256, B / 8), 256>>>();

    // output layout (float32): order (outcome, est, iters, conv)
    const long long n_out = B * F;                 // 256
    const long long n_est = (long long)B * F * D;  // 262144
    long long off_outcome = -1, off_est = -1, off_misc = -1;
    if ((long long)out_size >= n_out + n_est + 2) {
        off_outcome = 0; off_est = n_out; off_misc = n_out + n_est;
    } else if ((long long)out_size == n_est) {
        off_est = 0;
    } else if ((long long)out_size == n_out) {
        off_outcome = 0;
    } else if ((long long)out_size == n_out + n_est) {
        off_outcome = 0; off_est = n_out;
    } else {
        off_outcome = 0;
    }

    k_out<<<(B * F * D) / 256, 256>>>(
        off_outcome >= 0 ? out + off_outcome : nullptr,
        off_est     >= 0 ? out + off_est     : nullptr,
        off_misc    >= 0 ? out + off_misc    : nullptr);
}

// round 6
// speedup vs baseline: 6.6776x; 1.0017x over previous
#include <cuda_runtime.h>
#include <cuda_fp16.h>
#include <cstdint>

#define B 64
#define F 4
#define M 4096
#define D 1024
#define ITERS 15
#define WPD 16   // 64-bit words per D-dim vector
#define WPM 64   // 64-bit words per M-dim vector
#define FINAL_BUF (ITERS & 1)

// ---------------- device scratch (no allocs allowed) ----------------
__device__ unsigned long long g_cb_bits[F][WPD][M];   // codebook bits over d, [f][word][m] (2 MB)
__device__ unsigned long long g_cbcol[F][D][WPM];     // codebook bits over m, [f][d][word] (2 MB)
__device__ __half             g_G[F][D][D];           // Gram matrix C^T C, exact even ints (8 MB)
__device__ unsigned long long g_in_bits[B][WPD];
__device__ unsigned long long g_est[2][B][F][WPD];    // double-buffered estimates (bit 1 = -1)
__device__ int                g_key[B * F];           // argmax keys (atomicMax)
__device__ int                g_diff[ITERS];          // per-iteration "changed" flags

// ---------------- helpers ----------------
__device__ __forceinline__ unsigned long long pack64(const float* p) {
    unsigned long long w = 0ULL;
    #pragma unroll
    for (int t = 0; t < 16; t++) {
        float4 v = reinterpret_cast<const float4*>(p)[t];
        w |= ((unsigned long long)(v.x < 0.f)) << (4 * t + 0);
        w |= ((unsigned long long)(v.y < 0.f)) << (4 * t + 1);
        w |= ((unsigned long long)(v.z < 0.f)) << (4 * t + 2);
        w |= ((unsigned long long)(v.w < 0.f)) << (4 * t + 3);
    }
    return w;
}

__device__ __forceinline__ void mma16816(float* c,
                                         unsigned a0, unsigned a1, unsigned a2, unsigned a3,
                                         unsigned b0, unsigned b1) {
    asm volatile(
        "mma.sync.aligned.m16n8k16.row.col.f32.f16.f16.f32 "
        "{%0,%1,%2,%3}, {%4,%5,%6,%7}, {%8,%9}, {%0,%1,%2,%3};"
        : "+f"(c[0]), "+f"(c[1]), "+f"(c[2]), "+f"(c[3])
        : "r"(a0), "r"(a1), "r"(a2), "r"(a3), "r"(b0), "r"(b1));
}

// bits (2 low bits, 1 = negative) -> packed half2 {+-1, +-1}
__device__ __forceinline__ unsigned bits2h2(unsigned bits) {
    return 0x3C003C00u ^ ((bits & 1u) << 15) ^ ((bits & 2u) << 30);
}

// ---------------- packing kernels ----------------
__global__ void k_pack_small(const float* __restrict__ input,
                             const float* __restrict__ est0) {
    int idx = blockIdx.x * 256 + threadIdx.x;
    const int base = B * WPD + B * F * WPD;
    if (idx < B * WPD) {
        int b = idx >> 4, j = idx & 15;
        g_in_bits[b][j] = pack64(input + b * D + j * 64);
    } else if (idx < base) {
        int w = idx - B * WPD;
        int b = w >> 6, f = (w >> 4) & 3, j = w & 15;
        g_est[0][b][f][j] = pack64(est0 + (size_t)(b * F + f) * D + j * 64);
    } else if (idx < base + ITERS) {
        g_diff[idx - base] = 0;
    } else if (idx < base + ITERS + B * F) {
        g_key[idx - base - ITERS] = -1;
    }
}

__global__ void k_pack_cb(const float* __restrict__ cb) {
    int idx = blockIdx.x * 256 + threadIdx.x;   // F*WPD*M total
    int m = idx & (M - 1);
    int j = (idx >> 12) & 15;
    int f = idx >> 16;
    g_cb_bits[f][j][m] = pack64(cb + ((size_t)(f * M + m)) * D + j * 64);
}

// bits over m for each (f, d): g_cbcol[f][d][j], bit k <-> m = j*64+k
__global__ void k_pack_cbcol(const float* __restrict__ cb) {
    int idx = blockIdx.x * 256 + threadIdx.x;   // (f*WPM + j)*D + d
    int d = idx & (D - 1);
    int rest = idx >> 10;
    int j = rest & 63;
    int f = rest >> 6;
    const float* base = cb + ((size_t)f * M + (size_t)j * 64) * D + d;
    unsigned long long w = 0ULL;
    #pragma unroll
    for (int k = 0; k < 64; k++) {
        float v = base[(size_t)k * D];
        w |= ((unsigned long long)(v < 0.f)) << k;
    }
    g_cbcol[f][d][j] = w;
}

// ---------------- Gram: symmetric, 64x64 tiles, 4x4 per thread ----------------
__global__ void __launch_bounds__(256) k_gram2() {
    __shared__ unsigned long long shX[64][19];   // padded: conflict-free strided reads
    __shared__ unsigned long long shY[64][19];
    __shared__ __half stage[64][72];

    int f = blockIdx.x;
    int p = blockIdx.y;                 // triangular pair index, 136 per f
    int tx = 0;
    while (p >= 16 - tx) { p -= 16 - tx; tx++; }
    int ty = tx + p;
    int x0 = tx * 64, y0 = ty * 64;

    int tid = threadIdx.x;
    int u = (tid >> 4) * 4;             // x sub-row (0..60)
    int v = (tid & 15) * 4;             // y sub-row (0..60)

    int acc[4][4];
    #pragma unroll
    for (int i = 0; i < 4; i++)
        #pragma unroll
        for (int j = 0; j < 4; j++) acc[i][j] = 0;

    for (int kc = 0; kc < WPM; kc += 16) {
        #pragma unroll
        for (int r = 0; r < 4; r++) {
            int idx = tid + 256 * r;    // 1024 words
            int row = idx >> 4, w = idx & 15;
            shX[row][w] = g_cbcol[f][x0 + row][kc + w];
            shY[row][w] = g_cbcol[f][y0 + row][kc + w];
        }
        __syncthreads();
        #pragma unroll
        for (int w = 0; w < 16; w++) {
            unsigned long long x0v = shX[u    ][w];
            unsigned long long x1v = shX[u + 1][w];
            unsigned long long x2v = shX[u + 2][w];
            unsigned long long x3v = shX[u + 3][w];
            unsigned long long y0v = shY[v    ][w];
            unsigned long long y1v = shY[v + 1][w];
            unsigned long long y2v = shY[v + 2][w];
            unsigned long long y3v = shY[v + 3][w];
            acc[0][0] += __popcll(x0v ^ y0v); acc[0][1] += __popcll(x0v ^ y1v);
            acc[0][2] += __popcll(x0v ^ y2v); acc[0][3] += __popcll(x0v ^ y3v);
            acc[1][0] += __popcll(x1v ^ y0v); acc[1][1] += __popcll(x1v ^ y1v);
            acc[1][2] += __popcll(x1v ^ y2v); acc[1][3] += __popcll(x1v ^ y3v);
            acc[2][0] += __popcll(x2v ^ y0v); acc[2][1] += __popcll(x2v ^ y1v);
            acc[2][2] += __popcll(x2v ^ y2v); acc[2][3] += __popcll(x2v ^ y3v);
            acc[3][0] += __popcll(x3v ^ y0v); acc[3][1] += __popcll(x3v ^ y1v);
            acc[3][2] += __popcll(x3v ^ y2v); acc[3][3] += __popcll(x3v ^ y3v);
        }
        __syncthreads();
    }

    // stage tile (rows = x, cols = y)
    #pragma unroll
    for (int i = 0; i < 4; i++)
        #pragma unroll
        for (int j = 0; j < 4; j++)
            stage[u + i][v + j] = __int2half_rn(M - 2 * acc[i][j]);
    __syncthreads();

    // pass 1: G[x0+row][y0+col], coalesced
    #pragma unroll
    for (int r = 0; r < 2; r++) {
        int idx = tid + 256 * r;        // 512 uint4
        int row = idx >> 3, seg = idx & 7;
        *(uint4*)&g_G[f][x0 + row][y0 + seg * 8] = *(const uint4*)&stage[row][seg * 8];
    }

    // pass 2: transposed G[y0+r][x0+..] (skip for diagonal tiles)
    if (tx != ty) {
        int r = tid >> 2, qd = tid & 3;     // r: 0..63, qd: 0..3 (16-col quarters)
        unsigned wds[8];
        #pragma unroll
        for (int k = 0; k < 8; k++) {
            unsigned short h0 = __half_as_ushort(stage[qd * 16 + 2 * k    ][r]);
            unsigned short h1 = __half_as_ushort(stage[qd * 16 + 2 * k + 1][r]);
            wds[k] = ((unsigned)h1 << 16) | h0;
        }
        uint4 lo = make_uint4(wds[0], wds[1], wds[2], wds[3]);
        uint4 hi = make_uint4(wds[4], wds[5], wds[6], wds[7]);
        *(uint4*)&g_G[f][y0 + r][x0 + qd * 16    ] = lo;
        *(uint4*)&g_G[f][y0 + r][x0 + qd * 16 + 8] = hi;
    }
}

// ---------------- fused iteration kernel ----------------
// upd = sign(new_est @ G[f]), pack to bits, diff flag, double-buffered est.
// grid = (F, 16, 2), block = 256 (8 warps). Block tile: 32(B) x 64(d), K = D.
__global__ void __launch_bounds__(256) k_iter(int t) {
    const int rbuf = t & 1, wbuf = (t & 1) ^ 1;
    __shared__ unsigned long long snew[32][WPD + 1];   // new_est bits, this f / b-half
    __shared__ __align__(16) __half shB[64][72];       // G chunk [d][k]
    __shared__ unsigned char sbytes[32][64];           // sign bytes

    int f  = blockIdx.x;
    int jd = blockIdx.y;               // d-tile (64 d per word)
    int b0 = blockIdx.z * 32;          // batch half
    int tid = threadIdx.x;
    int wid = tid >> 5, lane = tid & 31, g = lane >> 2, q = lane & 3;
    int mrow0 = (wid >> 2) * 16;       // 2 row groups of 16
    int ncol0 = (wid & 3) * 16;        // 4 col groups of 16

    // new_est bits: in ^ (xor over all f) ^ est_f, 512 words
    #pragma unroll
    for (int r = 0; r < 2; r++) {
        int idx = tid + 256 * r;
        int bl = idx >> 4, j = idx & 15;
        int b = b0 + bl;
        unsigned long long tot = g_in_bits[b][j];
        #pragma unroll
        for (int ff = 0; ff < F; ff++) tot ^= g_est[rbuf][b][ff][j];
        snew[bl][j] = tot ^ g_est[rbuf][b][f][j];
    }
    __syncthreads();

    float acc[2][4];
    #pragma unroll
    for (int i = 0; i < 2; i++)
        #pragma unroll
        for (int jj = 0; jj < 4; jj++) acc[i][jj] = 0.f;

    const int d0 = jd * 64;
    for (int kc = 0; kc < D; kc += 64) {
        // load G chunk: 64 rows (d) x 64 halves (k) = 512 uint4, 2 per thread
        #pragma unroll
        for (int r = 0; r < 2; r++) {
            int idx = tid + 256 * r;
            int row = idx >> 3, seg = idx & 7;
            *(uint4*)&shB[row][seg * 8] =
                *(const uint4*)&g_G[f][d0 + row][kc + seg * 8];
        }
        __syncthreads();
        unsigned long long w0 = snew[mrow0 + g][kc >> 6];
        unsigned long long w1 = snew[mrow0 + 8 + g][kc >> 6];
        #pragma unroll
        for (int kk = 0; kk < 64; kk += 16) {
            unsigned a0 = bits2h2((unsigned)(w0 >> (kk + q * 2)) & 3u);
            unsigned a1 = bits2h2((unsigned)(w1 >> (kk + q * 2)) & 3u);
            unsigned a2 = bits2h2((unsigned)(w0 >> (kk + 8 + q * 2)) & 3u);
            unsigned a3 = bits2h2((unsigned)(w1 >> (kk + 8 + q * 2)) & 3u);
            #pragma unroll
            for (int nt = 0; nt < 2; nt++) {
                unsigned b0v = *(const unsigned*)&shB[ncol0 + nt * 8 + g][kk + q * 2];
                unsigned b1v = *(const unsigned*)&shB[ncol0 + nt * 8 + g][kk + 8 + q * 2];
                mma16816(acc[nt], a0, a1, a2, a3, b0v, b1v);
            }
        }
        __syncthreads();
    }

    // epilogue: sign bytes -> smem
    int r0 = mrow0 + g;
    #pragma unroll
    for (int nt = 0; nt < 2; nt++) {
        int c0 = ncol0 + nt * 8 + q * 2;
        sbytes[r0    ][c0    ] = (unsigned char)(acc[nt][0] < 0.f);
        sbytes[r0    ][c0 + 1] = (unsigned char)(acc[nt][1] < 0.f);
        sbytes[r0 + 8][c0    ] = (unsigned char)(acc[nt][2] < 0.f);
        sbytes[r0 + 8][c0 + 1] = (unsigned char)(acc[nt][3] < 0.f);
    }
    __syncthreads();

    if (tid < 32) {
        const unsigned long long* q8 = (const unsigned long long*)sbytes[tid];
        unsigned long long w = 0ULL;
        #pragma unroll
        for (int s = 0; s < 8; s++) {
            unsigned long long x = q8[s];
            #pragma unroll
            for (int k = 0; k < 8; k++)
                w |= ((x >> (8 * k)) & 1ULL) << (8 * s + k);
        }
        int b = b0 + tid;
        bool diff = (w != g_est[rbuf][b][f][jd]);
        g_est[wbuf][b][f][jd] = w;
        unsigned bal = __ballot_sync(0xffffffffu, diff);
        if (lane == 0 && bal) atomicOr(&g_diff[t], 1);
    }
}

// ---------------- cleanup: partial argmax over m-chunks via atomicMax ----------------
// grid = (F, M/256, B/8), block = 256
__global__ void k_cleanup() {
    int f = blockIdx.x;
    int m = blockIdx.y * 256 + threadIdx.x;
    int b0 = blockIdx.z * 8;
    __shared__ unsigned long long sh[8][WPD];
    __shared__ int skey[8][33];
    if (threadIdx.x < 128) {
        int bb = threadIdx.x >> 4, j = threadIdx.x & 15;
        sh[bb][j] = g_est[FINAL_BUF][b0 + bb][f][j];
    }
    __syncthreads();
    int acc[8];
    #pragma unroll
    for (int i = 0; i < 8; i++) acc[i] = 0;
    #pragma unroll
    for (int j = 0; j < WPD; j++) {
        unsigned long long w = g_cb_bits[f][j][m];
        #pragma unroll
        for (int bb = 0; bb < 8; bb++) acc[bb] += __popcll(w ^ sh[bb][j]);
    }
    // per-thread keys, warp-reduce, then atomicMax per (b,f)
    int lane = threadIdx.x & 31, wid = threadIdx.x >> 5;
    #pragma unroll
    for (int bb = 0; bb < 8; bb++) {
        int vv = D - 2 * acc[bb];
        int a = vv < 0 ? -vv : vv;
        int key = (a << 12) | (4095 - m);
        #pragma unroll
        for (int s = 16; s > 0; s >>= 1) {
            int o = __shfl_down_sync(0xffffffffu, key, s);
            if (o > key) key = o;
        }
        if (lane == 0) skey[bb][wid] = key;
    }
    __syncthreads();
    if (threadIdx.x < 8) {
        int bb = threadIdx.x;
        int best = skey[bb][0];
        #pragma unroll
        for (int w2 = 1; w2 < 8; w2++)
            if (skey[bb][w2] > best) best = skey[bb][w2];
        atomicMax(&g_key[(b0 + bb) * F + f], best);
    }
}

// ---------------- combined output kernel ----------------
__global__ void k_out(float* __restrict__ out_outcome,
                      float* __restrict__ out_est,
                      float* __restrict__ out_misc) {
    int idx = blockIdx.x * 256 + threadIdx.x;   // est: b*F*D + f*D + d
    if (out_est) {
        int d = idx & (D - 1);
        int f = (idx >> 10) & 3;
        int b = idx >> 12;
        unsigned long long w = g_est[FINAL_BUF][b][f][d >> 6];
        out_est[idx] = ((w >> (d & 63)) & 1ULL) ? -1.f : 1.f;
    }
    if (blockIdx.x == 0) {
        if (out_outcome && threadIdx.x < B * F)
            out_outcome[threadIdx.x] = (float)(4095 - (g_key[threadIdx.x] & 4095));
        if (out_misc && threadIdx.x == 0) {
            int iters = ITERS, conv = 0;
            for (int t = 0; t < ITERS; t++) {
                if (g_diff[t] == 0) { iters = t + 1; conv = 1; break; }
            }
            out_misc[0] = (float)iters;
            out_misc[1] = (float)conv;
        }
    }
}

// ---------------- launcher ----------------
extern "C" void kernel_launch(void* const* d_in, const int* in_sizes, int n_in,
                              void* d_out, int out_size) {
    const float* input = nullptr;
    const float* est0  = nullptr;
    const float* cb    = nullptr;
    for (int i = 0; i < n_in; i++) {
        if      (in_sizes[i] == B * D)     input = (const float*)d_in[i];
        else if (in_sizes[i] == B * F * D) est0  = (const float*)d_in[i];
        else if (in_sizes[i] == F * M * D) cb    = (const float*)d_in[i];
    }
    if (!input) input = (const float*)d_in[0];
    if (!est0)  est0  = (const float*)d_in[1];
    if (!cb)    cb    = (const float*)d_in[2];
    float* out = (float*)d_out;

    const int n_small = B * WPD + B * F * WPD + ITERS + B * F;
    k_pack_small<<<(n_small + 255) / 256, 256>>>(input, est0);
    k_pack_cb<<<F * WPD * M / 256, 256>>>(cb);
    k_pack_cbcol<<<F * WPM * D / 256, 256>>>(cb);
    k_gram2<<<dim3(F, 136), 256>>>();

    for (int t = 0; t < ITERS; t++) {
        k_iter<<<dim3(F, D / 64, 2), 256>>>(t);
    }

    k_cleanup<<<dim3(F, M / 256, B / 8), 256>>>();

    // output layout (float32): order (outcome, est, iters, conv)
    const long long n_out = B * F;                 // 256
    const long long n_est = (long long)B * F * D;  // 262144
    long long off_outcome = -1, off_est = -1, off_misc = -1;
    if ((long long)out_size >= n_out + n_est + 2) {
        off_outcome = 0; off_est = n_out; off_misc = n_out + n_est;
    } else if ((long long)out_size == n_est) {
        off_est = 0;
    } else if ((long long)out_size == n_out) {
        off_outcome = 0;
    } else if ((long long)out_size == n_out + n_est) {
        off_outcome = 0; off_est = n_out;
    } else {
        off_outcome = 0;
    }

    k_out<<<(B * F * D) / 256, 256>>>(
        off_outcome >= 0 ? out + off_outcome : nullptr,
        off_est     >= 0 ? out + off_est     : nullptr,
        off_misc    >= 0 ? out + off_misc    : nullptr);
}